// round 12
// baseline (speedup 1.0000x reference)
#include <cuda_runtime.h>
#include <cuda_bf16.h>
#include <math.h>
#include <stdint.h>

// Problem constants
constexpr int Bb = 4;
constexpr int Ss = 2048;
constexpr int Ee = 768;
constexpr int Hh = 12;
constexpr int Dd = 64;
constexpr int Mrows = Bb * Ss;      // 8192
constexpr int N_QKV = 3 * Ee;       // 2304
constexpr int Kdim = 768;

// Scratch (device globals: no allocation allowed)
__device__ float g_q[(size_t)Bb * Hh * Ss * Dd];
__device__ float g_k[(size_t)Bb * Hh * Ss * Dd];
__device__ float g_v[(size_t)Bb * Hh * Ss * Dd];
__device__ float g_y[(size_t)Bb * Ss * Ee];

// ---------------------------------------------------------------------------
// Raw-PTX bf16-split GEMM pieces (shared by the two plain kernels below).
// ---------------------------------------------------------------------------
constexpr int GBM = 128, GBN = 64, GBK = 32;
constexpr int A_LD  = GBK + 8;   // 40
constexpr int BT_LD = GBK + 8;   // 40

__device__ __forceinline__ uint32_t pack2(float v0, float v1) {
    __nv_bfloat162 t = __floats2bfloat162_rn(v0, v1);
    return *reinterpret_cast<uint32_t*>(&t);
}

__device__ __forceinline__ void mma_bf16(float d[4],
                                         const uint32_t a[4],
                                         const uint32_t b[2]) {
    asm volatile(
        "mma.sync.aligned.m16n8k16.row.col.f32.bf16.bf16.f32 "
        "{%0,%1,%2,%3}, {%4,%5,%6,%7}, {%8,%9}, {%0,%1,%2,%3};\n"
        : "+f"(d[0]), "+f"(d[1]), "+f"(d[2]), "+f"(d[3])
        : "r"(a[0]), "r"(a[1]), "r"(a[2]), "r"(a[3]),
          "r"(b[0]), "r"(b[1]));
}

// FMA-pipe exp: exp(x) = 2^(x*log2e), degree-6 poly on the fraction.
// Valid for x <= 0 (our case); x = -inf returns ~1e-38 (effectively 0).
__device__ __forceinline__ float fast_exp(float x) {
    float t = x * 1.4426950408889634f;
    t = fmaxf(t, -126.0f);
    const int n = __float2int_rn(t);
    const float f = t - (float)n;
    float p = 1.5403530393381609e-4f;          // (ln2)^6/720
    p = fmaf(p, f, 1.3333558146428443e-3f);    // (ln2)^5/120
    p = fmaf(p, f, 9.6181291976376165e-3f);    // (ln2)^4/24
    p = fmaf(p, f, 5.5504108664821580e-2f);    // (ln2)^3/6
    p = fmaf(p, f, 2.4022650695910072e-1f);    // (ln2)^2/2
    p = fmaf(p, f, 6.9314718055994531e-1f);    // ln2
    p = fmaf(p, f, 1.0f);
    return __int_as_float((n + 127) << 23) * p;
}

// ---------------------------------------------------------------------------
// Kernel 1: QKV = x @ W_attn + b_attn, scattered to [B,H,S,D]
// (byte-identical to R11-passing version)
// ---------------------------------------------------------------------------
__global__ __launch_bounds__(256) void qkv_gemm_kernel(
    const float* __restrict__ x,      // [M, 768]
    const float* __restrict__ W,      // [768, 2304]
    const float* __restrict__ bias)   // [2304]
{
    __shared__ __nv_bfloat16 Ah[GBM * A_LD];
    __shared__ __nv_bfloat16 Al[GBM * A_LD];
    __shared__ __nv_bfloat16 Bth[GBN * BT_LD];
    __shared__ __nv_bfloat16 Btl[GBN * BT_LD];

    const int tid = threadIdx.x;
    const int m0 = blockIdx.y * GBM;
    const int n0 = blockIdx.x * GBN;

    const int w    = tid >> 5;
    const int wm   = w >> 1;
    const int wn   = w & 1;
    const int lane = tid & 31;
    const int g    = lane >> 2;
    const int tg   = lane & 3;

    float acc[2][4][4] = {};

    for (int k0 = 0; k0 < Kdim; k0 += GBK) {
        #pragma unroll
        for (int p = 0; p < 4; p++) {
            const int id = p * 256 + tid;
            const int r = id >> 3;
            const int c4 = id & 7;
            const float4 v4 = *reinterpret_cast<const float4*>(
                x + (size_t)(m0 + r) * Kdim + k0 + c4 * 4);
            const float vv[4] = {v4.x, v4.y, v4.z, v4.w};
            float hi[4], lo[4];
            #pragma unroll
            for (int q = 0; q < 4; q++) {
                hi[q] = __bfloat162float(__float2bfloat16(vv[q]));
                lo[q] = vv[q] - hi[q];
            }
            uint32_t* ah32 = reinterpret_cast<uint32_t*>(Ah + r * A_LD + c4 * 4);
            uint32_t* al32 = reinterpret_cast<uint32_t*>(Al + r * A_LD + c4 * 4);
            ah32[0] = pack2(hi[0], hi[1]); ah32[1] = pack2(hi[2], hi[3]);
            al32[0] = pack2(lo[0], lo[1]); al32[1] = pack2(lo[2], lo[3]);
        }
        #pragma unroll
        for (int p = 0; p < 2; p++) {
            const int id = p * 256 + tid;
            const int r = id >> 4;
            const int c4 = id & 15;
            const float4 v4 = *reinterpret_cast<const float4*>(
                W + (size_t)(k0 + r) * N_QKV + n0 + c4 * 4);
            const float vv[4] = {v4.x, v4.y, v4.z, v4.w};
            #pragma unroll
            for (int q = 0; q < 4; q++) {
                const float h = __bfloat162float(__float2bfloat16(vv[q]));
                const float l = vv[q] - h;
                Bth[(c4 * 4 + q) * BT_LD + r] = __float2bfloat16(h);
                Btl[(c4 * 4 + q) * BT_LD + r] = __float2bfloat16(l);
            }
        }
        __syncthreads();

        #pragma unroll
        for (int ks = 0; ks < 2; ks++) {
            const int kk = ks * 16;
            uint32_t ahf[2][4], alf[2][4];
            #pragma unroll
            for (int i = 0; i < 2; i++) {
                const int br = wm * 32 + i * 16;
                ahf[i][0] = *reinterpret_cast<const uint32_t*>(Ah + (br + g)     * A_LD + kk + tg * 2);
                ahf[i][1] = *reinterpret_cast<const uint32_t*>(Ah + (br + g + 8) * A_LD + kk + tg * 2);
                ahf[i][2] = *reinterpret_cast<const uint32_t*>(Ah + (br + g)     * A_LD + kk + tg * 2 + 8);
                ahf[i][3] = *reinterpret_cast<const uint32_t*>(Ah + (br + g + 8) * A_LD + kk + tg * 2 + 8);
                alf[i][0] = *reinterpret_cast<const uint32_t*>(Al + (br + g)     * A_LD + kk + tg * 2);
                alf[i][1] = *reinterpret_cast<const uint32_t*>(Al + (br + g + 8) * A_LD + kk + tg * 2);
                alf[i][2] = *reinterpret_cast<const uint32_t*>(Al + (br + g)     * A_LD + kk + tg * 2 + 8);
                alf[i][3] = *reinterpret_cast<const uint32_t*>(Al + (br + g + 8) * A_LD + kk + tg * 2 + 8);
            }
            uint32_t bhf[4][2], blf[4][2];
            #pragma unroll
            for (int j = 0; j < 4; j++) {
                const int n = wn * 32 + j * 8 + g;
                bhf[j][0] = *reinterpret_cast<const uint32_t*>(Bth + n * BT_LD + kk + tg * 2);
                bhf[j][1] = *reinterpret_cast<const uint32_t*>(Bth + n * BT_LD + kk + tg * 2 + 8);
                blf[j][0] = *reinterpret_cast<const uint32_t*>(Btl + n * BT_LD + kk + tg * 2);
                blf[j][1] = *reinterpret_cast<const uint32_t*>(Btl + n * BT_LD + kk + tg * 2 + 8);
            }
            #pragma unroll
            for (int i = 0; i < 2; i++)
                #pragma unroll
                for (int j = 0; j < 4; j++) {
                    mma_bf16(acc[i][j], ahf[i], bhf[j]);
                    mma_bf16(acc[i][j], ahf[i], blf[j]);
                    mma_bf16(acc[i][j], alf[i], bhf[j]);
                }
        }
        __syncthreads();
    }

    #pragma unroll
    for (int i = 0; i < 2; i++) {
        #pragma unroll
        for (int j = 0; j < 4; j++) {
            const int colb = n0 + wn * 32 + j * 8 + tg * 2;
            #pragma unroll
            for (int e4 = 0; e4 < 4; e4++) {
                const int m = m0 + wm * 32 + i * 16 + g + (e4 >= 2 ? 8 : 0);
                const int n = colb + (e4 & 1);
                const float val = acc[i][j][e4] + bias[n];
                const int b = m >> 11;
                const int s = m & 2047;
                const int which = n / Ee;
                const int e = n - which * Ee;
                const int h = e >> 6;
                const int d = e & 63;
                const size_t idx = (((size_t)(b * Hh + h)) * Ss + s) * Dd + d;
                float* dst = (which == 0) ? g_q : (which == 1) ? g_k : g_v;
                dst[idx] = val;
            }
        }
    }
}

// ---------------------------------------------------------------------------
// Kernel 2: flash-style causal attention, 128-query x 64-key tiles.
// Same as R10/R11-passing version except __expf -> fast_exp (FMA pipe).
// ---------------------------------------------------------------------------
constexpr int ATT_LD = 65;
constexpr int QROWS = 128;
constexpr size_t ATT_SMEM_BYTES =
    (size_t)(QROWS * ATT_LD + 64 * ATT_LD + 64 * ATT_LD + QROWS * ATT_LD) * sizeof(float); // 99840

__global__ __launch_bounds__(256) void attn_kernel(const int* __restrict__ att_mask)
{
    extern __shared__ float sm[];
    float* Qs = sm;                                    // [128][65]
    float* Ks = sm + QROWS * ATT_LD;                   // [64][65]
    float* Vs = sm + QROWS * ATT_LD + 64 * ATT_LD;     // [64][65]
    float* Ps = sm + QROWS * ATT_LD + 2 * 64 * ATT_LD; // [128][65]

    const int tid = threadIdx.x;
    const int tx = tid & 15;
    const int ty = tid >> 4;
    const int qb = blockIdx.x;          // 0..15
    const int h = blockIdx.y;
    const int b = blockIdx.z;
    const size_t head_base = ((size_t)(b * Hh + h)) * Ss * Dd;
    const int q0 = qb * QROWS;

    #pragma unroll
    for (int p = 0; p < 8; p++) {
        const int lin = p * 256 + tid;
        const int r = lin >> 4;
        const int c4 = lin & 15;
        const float4 v4 = *reinterpret_cast<const float4*>(
            g_q + head_base + (size_t)(q0 + r) * Dd + c4 * 4);
        Qs[r * ATT_LD + c4 * 4 + 0] = v4.x;
        Qs[r * ATT_LD + c4 * 4 + 1] = v4.y;
        Qs[r * ATT_LD + c4 * 4 + 2] = v4.z;
        Qs[r * ATT_LD + c4 * 4 + 3] = v4.w;
    }

    float m_i[8], l_i[8];
    float acc[8][4] = {};
    #pragma unroll
    for (int i = 0; i < 8; i++) { m_i[i] = -INFINITY; l_i[i] = 0.0f; }

    const int jmax = 2 * qb + 1;
    for (int j = 0; j <= jmax; j++) {
        __syncthreads();
        #pragma unroll
        for (int p = 0; p < 4; p++) {
            const int lin = p * 256 + tid;
            const int r = lin >> 4;
            const int c4 = lin & 15;
            const size_t off = head_base + (size_t)(j * 64 + r) * Dd + c4 * 4;
            const float4 k4 = *reinterpret_cast<const float4*>(g_k + off);
            const float4 v4 = *reinterpret_cast<const float4*>(g_v + off);
            Ks[r * ATT_LD + c4 * 4 + 0] = k4.x;
            Ks[r * ATT_LD + c4 * 4 + 1] = k4.y;
            Ks[r * ATT_LD + c4 * 4 + 2] = k4.z;
            Ks[r * ATT_LD + c4 * 4 + 3] = k4.w;
            Vs[r * ATT_LD + c4 * 4 + 0] = v4.x;
            Vs[r * ATT_LD + c4 * 4 + 1] = v4.y;
            Vs[r * ATT_LD + c4 * 4 + 2] = v4.z;
            Vs[r * ATT_LD + c4 * 4 + 3] = v4.w;
        }
        __syncthreads();

        float s[8][4] = {};
        #pragma unroll 8
        for (int kk = 0; kk < Dd; kk++) {
            float a[8], bbk[4];
            #pragma unroll
            for (int i = 0; i < 8; i++) a[i] = Qs[(ty * 8 + i) * ATT_LD + kk];
            #pragma unroll
            for (int jj = 0; jj < 4; jj++) bbk[jj] = Ks[(tx * 4 + jj) * ATT_LD + kk];
            #pragma unroll
            for (int i = 0; i < 8; i++)
                #pragma unroll
                for (int jj = 0; jj < 4; jj++)
                    s[i][jj] = fmaf(a[i], bbk[jj], s[i][jj]);
        }

        const int kbase = j * 64 + tx * 4;
        int mk[4];
        #pragma unroll
        for (int jj = 0; jj < 4; jj++) mk[jj] = att_mask[b * Ss + kbase + jj];

        #pragma unroll
        for (int i = 0; i < 8; i++) {
            const int qg = q0 + ty * 8 + i;
            #pragma unroll
            for (int jj = 0; jj < 4; jj++) {
                const int kg = kbase + jj;
                s[i][jj] = (kg <= qg && mk[jj] != 0) ? s[i][jj] * 0.125f : -INFINITY;
            }
        }

        #pragma unroll
        for (int i = 0; i < 8; i++) {
            float rm = fmaxf(fmaxf(s[i][0], s[i][1]), fmaxf(s[i][2], s[i][3]));
            #pragma unroll
            for (int off = 8; off >= 1; off >>= 1)
                rm = fmaxf(rm, __shfl_xor_sync(0xffffffffu, rm, off));
            const float mn = fmaxf(m_i[i], rm);
            const float alpha = fast_exp(m_i[i] - mn);   // -inf -> ~0 on first tile
            float p[4];
            float rs = 0.0f;
            #pragma unroll
            for (int jj = 0; jj < 4; jj++) {
                p[jj] = fast_exp(s[i][jj] - mn);          // masked -> ~0
                rs += p[jj];
            }
            #pragma unroll
            for (int off = 8; off >= 1; off >>= 1)
                rs += __shfl_xor_sync(0xffffffffu, rs, off);
            l_i[i] = l_i[i] * alpha + rs;
            m_i[i] = mn;
            #pragma unroll
            for (int jj = 0; jj < 4; jj++) acc[i][jj] *= alpha;
            #pragma unroll
            for (int jj = 0; jj < 4; jj++)
                Ps[(ty * 8 + i) * ATT_LD + tx * 4 + jj] = p[jj];
        }
        __syncthreads();

        #pragma unroll 8
        for (int kk = 0; kk < 64; kk++) {
            float pi[8], vj[4];
            #pragma unroll
            for (int i = 0; i < 8; i++) pi[i] = Ps[(ty * 8 + i) * ATT_LD + kk];
            #pragma unroll
            for (int jj = 0; jj < 4; jj++) vj[jj] = Vs[kk * ATT_LD + tx * 4 + jj];
            #pragma unroll
            for (int i = 0; i < 8; i++)
                #pragma unroll
                for (int jj = 0; jj < 4; jj++)
                    acc[i][jj] = fmaf(pi[i], vj[jj], acc[i][jj]);
        }
    }

    #pragma unroll
    for (int i = 0; i < 8; i++) {
        const float inv = 1.0f / l_i[i];
        const int qg = q0 + ty * 8 + i;
        const size_t row = ((size_t)(b * Ss + qg)) * Ee + h * 64;
        #pragma unroll
        for (int jj = 0; jj < 4; jj++)
            g_y[row + tx * 4 + jj] = acc[i][jj] * inv;
    }
}

// ---------------------------------------------------------------------------
// Kernel 3: out = y @ W_proj + b_proj (byte-identical to R11-passing)
// ---------------------------------------------------------------------------
__global__ __launch_bounds__(256) void proj_gemm_kernel(
    const float* __restrict__ W,      // [768, 768]
    const float* __restrict__ bias,   // [768]
    float* __restrict__ out)          // [M, 768]
{
    __shared__ __nv_bfloat16 Ah[GBM * A_LD];
    __shared__ __nv_bfloat16 Al[GBM * A_LD];
    __shared__ __nv_bfloat16 Bth[GBN * BT_LD];
    __shared__ __nv_bfloat16 Btl[GBN * BT_LD];

    const int tid = threadIdx.x;
    const int m0 = blockIdx.y * GBM;
    const int n0 = blockIdx.x * GBN;

    const int w    = tid >> 5;
    const int wm   = w >> 1;
    const int wn   = w & 1;
    const int lane = tid & 31;
    const int g    = lane >> 2;
    const int tg   = lane & 3;

    float acc[2][4][4] = {};

    for (int k0 = 0; k0 < Kdim; k0 += GBK) {
        #pragma unroll
        for (int p = 0; p < 4; p++) {
            const int id = p * 256 + tid;
            const int r = id >> 3;
            const int c4 = id & 7;
            const float4 v4 = *reinterpret_cast<const float4*>(
                g_y + (size_t)(m0 + r) * Kdim + k0 + c4 * 4);
            const float vv[4] = {v4.x, v4.y, v4.z, v4.w};
            float hi[4], lo[4];
            #pragma unroll
            for (int q = 0; q < 4; q++) {
                hi[q] = __bfloat162float(__float2bfloat16(vv[q]));
                lo[q] = vv[q] - hi[q];
            }
            uint32_t* ah32 = reinterpret_cast<uint32_t*>(Ah + r * A_LD + c4 * 4);
            uint32_t* al32 = reinterpret_cast<uint32_t*>(Al + r * A_LD + c4 * 4);
            ah32[0] = pack2(hi[0], hi[1]); ah32[1] = pack2(hi[2], hi[3]);
            al32[0] = pack2(lo[0], lo[1]); al32[1] = pack2(lo[2], lo[3]);
        }
        #pragma unroll
        for (int p = 0; p < 2; p++) {
            const int id = p * 256 + tid;
            const int r = id >> 4;
            const int c4 = id & 15;
            const float4 v4 = *reinterpret_cast<const float4*>(
                W + (size_t)(k0 + r) * Ee + n0 + c4 * 4);
            const float vv[4] = {v4.x, v4.y, v4.z, v4.w};
            #pragma unroll
            for (int q = 0; q < 4; q++) {
                const float h = __bfloat162float(__float2bfloat16(vv[q]));
                const float l = vv[q] - h;
                Bth[(c4 * 4 + q) * BT_LD + r] = __float2bfloat16(h);
                Btl[(c4 * 4 + q) * BT_LD + r] = __float2bfloat16(l);
            }
        }
        __syncthreads();

        #pragma unroll
        for (int ks = 0; ks < 2; ks++) {
            const int kk = ks * 16;
            uint32_t ahf[2][4], alf[2][4];
            #pragma unroll
            for (int i = 0; i < 2; i++) {
                const int br = wm * 32 + i * 16;
                ahf[i][0] = *reinterpret_cast<const uint32_t*>(Ah + (br + g)     * A_LD + kk + tg * 2);
                ahf[i][1] = *reinterpret_cast<const uint32_t*>(Ah + (br + g + 8) * A_LD + kk + tg * 2);
                ahf[i][2] = *reinterpret_cast<const uint32_t*>(Ah + (br + g)     * A_LD + kk + tg * 2 + 8);
                ahf[i][3] = *reinterpret_cast<const uint32_t*>(Ah + (br + g + 8) * A_LD + kk + tg * 2 + 8);
                alf[i][0] = *reinterpret_cast<const uint32_t*>(Al + (br + g)     * A_LD + kk + tg * 2);
                alf[i][1] = *reinterpret_cast<const uint32_t*>(Al + (br + g + 8) * A_LD + kk + tg * 2);
                alf[i][2] = *reinterpret_cast<const uint32_t*>(Al + (br + g)     * A_LD + kk + tg * 2 + 8);
                alf[i][3] = *reinterpret_cast<const uint32_t*>(Al + (br + g + 8) * A_LD + kk + tg * 2 + 8);
            }
            uint32_t bhf[4][2], blf[4][2];
            #pragma unroll
            for (int j = 0; j < 4; j++) {
                const int n = wn * 32 + j * 8 + g;
                bhf[j][0] = *reinterpret_cast<const uint32_t*>(Bth + n * BT_LD + kk + tg * 2);
                bhf[j][1] = *reinterpret_cast<const uint32_t*>(Bth + n * BT_LD + kk + tg * 2 + 8);
                blf[j][0] = *reinterpret_cast<const uint32_t*>(Btl + n * BT_LD + kk + tg * 2);
                blf[j][1] = *reinterpret_cast<const uint32_t*>(Btl + n * BT_LD + kk + tg * 2 + 8);
            }
            #pragma unroll
            for (int i = 0; i < 2; i++)
                #pragma unroll
                for (int j = 0; j < 4; j++) {
                    mma_bf16(acc[i][j], ahf[i], bhf[j]);
                    mma_bf16(acc[i][j], ahf[i], blf[j]);
                    mma_bf16(acc[i][j], alf[i], bhf[j]);
                }
        }
        __syncthreads();
    }

    #pragma unroll
    for (int i = 0; i < 2; i++) {
        #pragma unroll
        for (int j = 0; j < 4; j++) {
            const int colb = n0 + wn * 32 + j * 8 + tg * 2;
            #pragma unroll
            for (int e4 = 0; e4 < 4; e4++) {
                const int m = m0 + wm * 32 + i * 16 + g + (e4 >= 2 ? 8 : 0);
                const int n = colb + (e4 & 1);
                out[(size_t)m * Ee + n] = acc[i][j][e4] + bias[n];
            }
        }
    }
}

// ---------------------------------------------------------------------------
// Launch
// ---------------------------------------------------------------------------
extern "C" void kernel_launch(void* const* d_in, const int* in_sizes, int n_in,
                              void* d_out, int out_size)
{
    const float* x      = (const float*)d_in[0];  // [B,S,E]
    const float* W_attn = (const float*)d_in[1];  // [E,3E]
    const float* b_attn = (const float*)d_in[2];  // [3E]
    const float* W_proj = (const float*)d_in[3];  // [E,E]
    const float* b_proj = (const float*)d_in[4];  // [E]
    const int* att_mask = (const int*)d_in[5];    // [B,S]
    float* out = (float*)d_out;

    // Opt-in to >48KB dynamic smem for the attention kernel (idempotent)
    cudaFuncSetAttribute(attn_kernel,
                         cudaFuncAttributeMaxDynamicSharedMemorySize,
                         (int)ATT_SMEM_BYTES);

    {
        dim3 grid(N_QKV / GBN, Mrows / GBM);   // 36 x 64
        qkv_gemm_kernel<<<grid, 256>>>(x, W_attn, b_attn);
    }
    {
        dim3 grid(Ss / QROWS, Hh, Bb);         // 16 x 12 x 4
        attn_kernel<<<grid, 256, ATT_SMEM_BYTES>>>(att_mask);
    }
    {
        dim3 grid(Ee / GBN, Mrows / GBM);      // 12 x 64
        proj_gemm_kernel<<<grid, 256>>>(W_proj, b_proj, out);
    }
}

// round 13
// speedup vs baseline: 1.5040x; 1.5040x over previous
#include <cuda_runtime.h>
#include <cuda_bf16.h>
#include <math.h>
#include <stdint.h>

// Problem constants
constexpr int Bb = 4;
constexpr int Ss = 2048;
constexpr int Ee = 768;
constexpr int Hh = 12;
constexpr int Dd = 64;
constexpr int Mrows = Bb * Ss;      // 8192
constexpr int N_QKV = 3 * Ee;       // 2304
constexpr int Kdim = 768;

// Scratch (device globals: no allocation allowed)
__device__ float g_q[(size_t)Bb * Hh * Ss * Dd];
__device__ float g_k[(size_t)Bb * Hh * Ss * Dd];
__device__ float g_v[(size_t)Bb * Hh * Ss * Dd];
__device__ float g_y[(size_t)Bb * Ss * Ee];

// ---------------------------------------------------------------------------
// Raw-PTX bf16-split GEMM pieces (hardware-validated in R11).
// ---------------------------------------------------------------------------
constexpr int GBM = 128, GBN = 64, GBK = 32;
constexpr int A_LD  = GBK + 8;   // 40
constexpr int BT_LD = GBK + 8;   // 40

__device__ __forceinline__ uint32_t pack2(float v0, float v1) {
    __nv_bfloat162 t = __floats2bfloat162_rn(v0, v1);
    return *reinterpret_cast<uint32_t*>(&t);
}

__device__ __forceinline__ void mma_bf16(float d[4],
                                         const uint32_t a[4],
                                         const uint32_t b[2]) {
    asm volatile(
        "mma.sync.aligned.m16n8k16.row.col.f32.bf16.bf16.f32 "
        "{%0,%1,%2,%3}, {%4,%5,%6,%7}, {%8,%9}, {%0,%1,%2,%3};\n"
        : "+f"(d[0]), "+f"(d[1]), "+f"(d[2]), "+f"(d[3])
        : "r"(a[0]), "r"(a[1]), "r"(a[2]), "r"(a[3]),
          "r"(b[0]), "r"(b[1]));
}

// ---------------------------------------------------------------------------
// Kernel 1: QKV = x @ W_attn + b_attn, scattered to [B,H,S,D]
// (byte-identical to R11-passing version)
// ---------------------------------------------------------------------------
__global__ __launch_bounds__(256) void qkv_gemm_kernel(
    const float* __restrict__ x,      // [M, 768]
    const float* __restrict__ W,      // [768, 2304]
    const float* __restrict__ bias)   // [2304]
{
    __shared__ __nv_bfloat16 Ah[GBM * A_LD];
    __shared__ __nv_bfloat16 Al[GBM * A_LD];
    __shared__ __nv_bfloat16 Bth[GBN * BT_LD];
    __shared__ __nv_bfloat16 Btl[GBN * BT_LD];

    const int tid = threadIdx.x;
    const int m0 = blockIdx.y * GBM;
    const int n0 = blockIdx.x * GBN;

    const int w    = tid >> 5;
    const int wm   = w >> 1;
    const int wn   = w & 1;
    const int lane = tid & 31;
    const int g    = lane >> 2;
    const int tg   = lane & 3;

    float acc[2][4][4] = {};

    for (int k0 = 0; k0 < Kdim; k0 += GBK) {
        #pragma unroll
        for (int p = 0; p < 4; p++) {
            const int id = p * 256 + tid;
            const int r = id >> 3;
            const int c4 = id & 7;
            const float4 v4 = *reinterpret_cast<const float4*>(
                x + (size_t)(m0 + r) * Kdim + k0 + c4 * 4);
            const float vv[4] = {v4.x, v4.y, v4.z, v4.w};
            float hi[4], lo[4];
            #pragma unroll
            for (int q = 0; q < 4; q++) {
                hi[q] = __bfloat162float(__float2bfloat16(vv[q]));
                lo[q] = vv[q] - hi[q];
            }
            uint32_t* ah32 = reinterpret_cast<uint32_t*>(Ah + r * A_LD + c4 * 4);
            uint32_t* al32 = reinterpret_cast<uint32_t*>(Al + r * A_LD + c4 * 4);
            ah32[0] = pack2(hi[0], hi[1]); ah32[1] = pack2(hi[2], hi[3]);
            al32[0] = pack2(lo[0], lo[1]); al32[1] = pack2(lo[2], lo[3]);
        }
        #pragma unroll
        for (int p = 0; p < 2; p++) {
            const int id = p * 256 + tid;
            const int r = id >> 4;
            const int c4 = id & 15;
            const float4 v4 = *reinterpret_cast<const float4*>(
                W + (size_t)(k0 + r) * N_QKV + n0 + c4 * 4);
            const float vv[4] = {v4.x, v4.y, v4.z, v4.w};
            #pragma unroll
            for (int q = 0; q < 4; q++) {
                const float h = __bfloat162float(__float2bfloat16(vv[q]));
                const float l = vv[q] - h;
                Bth[(c4 * 4 + q) * BT_LD + r] = __float2bfloat16(h);
                Btl[(c4 * 4 + q) * BT_LD + r] = __float2bfloat16(l);
            }
        }
        __syncthreads();

        #pragma unroll
        for (int ks = 0; ks < 2; ks++) {
            const int kk = ks * 16;
            uint32_t ahf[2][4], alf[2][4];
            #pragma unroll
            for (int i = 0; i < 2; i++) {
                const int br = wm * 32 + i * 16;
                ahf[i][0] = *reinterpret_cast<const uint32_t*>(Ah + (br + g)     * A_LD + kk + tg * 2);
                ahf[i][1] = *reinterpret_cast<const uint32_t*>(Ah + (br + g + 8) * A_LD + kk + tg * 2);
                ahf[i][2] = *reinterpret_cast<const uint32_t*>(Ah + (br + g)     * A_LD + kk + tg * 2 + 8);
                ahf[i][3] = *reinterpret_cast<const uint32_t*>(Ah + (br + g + 8) * A_LD + kk + tg * 2 + 8);
                alf[i][0] = *reinterpret_cast<const uint32_t*>(Al + (br + g)     * A_LD + kk + tg * 2);
                alf[i][1] = *reinterpret_cast<const uint32_t*>(Al + (br + g + 8) * A_LD + kk + tg * 2);
                alf[i][2] = *reinterpret_cast<const uint32_t*>(Al + (br + g)     * A_LD + kk + tg * 2 + 8);
                alf[i][3] = *reinterpret_cast<const uint32_t*>(Al + (br + g + 8) * A_LD + kk + tg * 2 + 8);
            }
            uint32_t bhf[4][2], blf[4][2];
            #pragma unroll
            for (int j = 0; j < 4; j++) {
                const int n = wn * 32 + j * 8 + g;
                bhf[j][0] = *reinterpret_cast<const uint32_t*>(Bth + n * BT_LD + kk + tg * 2);
                bhf[j][1] = *reinterpret_cast<const uint32_t*>(Bth + n * BT_LD + kk + tg * 2 + 8);
                blf[j][0] = *reinterpret_cast<const uint32_t*>(Btl + n * BT_LD + kk + tg * 2);
                blf[j][1] = *reinterpret_cast<const uint32_t*>(Btl + n * BT_LD + kk + tg * 2 + 8);
            }
            #pragma unroll
            for (int i = 0; i < 2; i++)
                #pragma unroll
                for (int j = 0; j < 4; j++) {
                    mma_bf16(acc[i][j], ahf[i], bhf[j]);
                    mma_bf16(acc[i][j], ahf[i], blf[j]);
                    mma_bf16(acc[i][j], alf[i], bhf[j]);
                }
        }
        __syncthreads();
    }

    #pragma unroll
    for (int i = 0; i < 2; i++) {
        #pragma unroll
        for (int j = 0; j < 4; j++) {
            const int colb = n0 + wn * 32 + j * 8 + tg * 2;
            #pragma unroll
            for (int e4 = 0; e4 < 4; e4++) {
                const int m = m0 + wm * 32 + i * 16 + g + (e4 >= 2 ? 8 : 0);
                const int n = colb + (e4 & 1);
                const float val = acc[i][j][e4] + bias[n];
                const int b = m >> 11;
                const int s = m & 2047;
                const int which = n / Ee;
                const int e = n - which * Ee;
                const int h = e >> 6;
                const int d = e & 63;
                const size_t idx = (((size_t)(b * Hh + h)) * Ss + s) * Dd + d;
                float* dst = (which == 0) ? g_q : (which == 1) ? g_k : g_v;
                dst[idx] = val;
            }
        }
    }
}

// ---------------------------------------------------------------------------
// Kernel 2: tensor-core flash attention. 128-query x 64-key tiles.
// 8 warps, each owns 16 q-rows (warp tile m16 x n64). bf16 hi/lo 3-term mma
// for both S=QK^T and O+=PV. P stays in registers (S-accum layout == PV
// A-fragment layout). Softmax rows reduced via quad shuffles.
// ---------------------------------------------------------------------------
constexpr int QROWS = 128;
constexpr int AT_LD = 72;   // 64 + 8 pad, bf16 elems
// bf16-element offsets into dynamic smem
constexpr int OFF_QH = 0;
constexpr int OFF_QL = OFF_QH + QROWS * AT_LD;    // 9216
constexpr int OFF_KH = OFF_QL + QROWS * AT_LD;    // 18432
constexpr int OFF_KL = OFF_KH + 64 * AT_LD;       // 23040
constexpr int OFF_VH = OFF_KL + 64 * AT_LD;       // 27648
constexpr int OFF_VL = OFF_VH + 64 * AT_LD;       // 32256
constexpr size_t ATT_SMEM_BYTES = (size_t)(OFF_VL + 64 * AT_LD) * 2;  // 73728 B

__global__ __launch_bounds__(256) void attn_kernel(const int* __restrict__ att_mask)
{
    extern __shared__ __nv_bfloat16 smb[];
    __nv_bfloat16* Qh = smb + OFF_QH;   // [128][72]  [m][k]
    __nv_bfloat16* Ql = smb + OFF_QL;
    __nv_bfloat16* Kh = smb + OFF_KH;   // [64][72]   [key][d] == B [n][k]
    __nv_bfloat16* Kl = smb + OFF_KL;
    __nv_bfloat16* Vh = smb + OFF_VH;   // [64][72]   transposed [d][key] == B [n][k]
    __nv_bfloat16* Vl = smb + OFF_VL;

    const int tid  = threadIdx.x;
    const int wp   = tid >> 5;      // warp 0..7 -> q rows wp*16..wp*16+15
    const int lane = tid & 31;
    const int g    = lane >> 2;     // 0..7
    const int tg   = lane & 3;      // 0..3

    const int qb = blockIdx.x;      // 0..15
    const int h  = blockIdx.y;
    const int b  = blockIdx.z;
    const size_t head_base = ((size_t)(b * Hh + h)) * Ss * Dd;
    const int q0 = qb * QROWS;

    // Load + split Q tile [128][64] (2048 float4, 8 per thread)
    #pragma unroll
    for (int p = 0; p < 8; p++) {
        const int id = p * 256 + tid;
        const int r = id >> 4;
        const int c4 = id & 15;
        const float4 v4 = *reinterpret_cast<const float4*>(
            g_q + head_base + (size_t)(q0 + r) * Dd + c4 * 4);
        const float vv[4] = {v4.x, v4.y, v4.z, v4.w};
        float hi[4], lo[4];
        #pragma unroll
        for (int q = 0; q < 4; q++) {
            hi[q] = __bfloat162float(__float2bfloat16(vv[q]));
            lo[q] = vv[q] - hi[q];
        }
        uint32_t* qh32 = reinterpret_cast<uint32_t*>(Qh + r * AT_LD + c4 * 4);
        uint32_t* ql32 = reinterpret_cast<uint32_t*>(Ql + r * AT_LD + c4 * 4);
        qh32[0] = pack2(hi[0], hi[1]); qh32[1] = pack2(hi[2], hi[3]);
        ql32[0] = pack2(lo[0], lo[1]); ql32[1] = pack2(lo[2], lo[3]);
    }

    float m0 = -INFINITY, m1 = -INFINITY, l0 = 0.0f, l1 = 0.0f;
    float acc_o[8][4] = {};

    const int jmax = 2 * qb + 1;
    for (int j = 0; j <= jmax; j++) {
        __syncthreads();   // prior iteration done reading K/V (also orders Q store)
        // Load + split K,V tiles (1024 float4 each, 4 per thread)
        #pragma unroll
        for (int p = 0; p < 4; p++) {
            const int id = p * 256 + tid;
            const int r = id >> 4;          // key 0..63
            const int c4 = id & 15;         // d group
            const size_t off = head_base + (size_t)(j * 64 + r) * Dd + c4 * 4;
            const float4 k4 = *reinterpret_cast<const float4*>(g_k + off);
            const float kv[4] = {k4.x, k4.y, k4.z, k4.w};
            float khv[4], klv[4];
            #pragma unroll
            for (int q = 0; q < 4; q++) {
                khv[q] = __bfloat162float(__float2bfloat16(kv[q]));
                klv[q] = kv[q] - khv[q];
            }
            uint32_t* kh32 = reinterpret_cast<uint32_t*>(Kh + r * AT_LD + c4 * 4);
            uint32_t* kl32 = reinterpret_cast<uint32_t*>(Kl + r * AT_LD + c4 * 4);
            kh32[0] = pack2(khv[0], khv[1]); kh32[1] = pack2(khv[2], khv[3]);
            kl32[0] = pack2(klv[0], klv[1]); kl32[1] = pack2(klv[2], klv[3]);

            const float4 v4 = *reinterpret_cast<const float4*>(g_v + off);
            const float vv[4] = {v4.x, v4.y, v4.z, v4.w};
            #pragma unroll
            for (int q = 0; q < 4; q++) {
                const float hv = __bfloat162float(__float2bfloat16(vv[q]));
                const float lv = vv[q] - hv;
                Vh[(c4 * 4 + q) * AT_LD + r] = __float2bfloat16(hv);
                Vl[(c4 * 4 + q) * AT_LD + r] = __float2bfloat16(lv);
            }
        }
        __syncthreads();

        // ---- S = Q K^T : warp tile m16 (rows wp*16..+15) x n64, k=64 ----
        float s[8][4] = {};
        #pragma unroll
        for (int kb = 0; kb < 4; kb++) {
            const int kk = kb * 16;
            uint32_t ah[4], al[4];
            const int br = wp * 16;
            ah[0] = *reinterpret_cast<const uint32_t*>(Qh + (br + g)     * AT_LD + kk + tg * 2);
            ah[1] = *reinterpret_cast<const uint32_t*>(Qh + (br + g + 8) * AT_LD + kk + tg * 2);
            ah[2] = *reinterpret_cast<const uint32_t*>(Qh + (br + g)     * AT_LD + kk + tg * 2 + 8);
            ah[3] = *reinterpret_cast<const uint32_t*>(Qh + (br + g + 8) * AT_LD + kk + tg * 2 + 8);
            al[0] = *reinterpret_cast<const uint32_t*>(Ql + (br + g)     * AT_LD + kk + tg * 2);
            al[1] = *reinterpret_cast<const uint32_t*>(Ql + (br + g + 8) * AT_LD + kk + tg * 2);
            al[2] = *reinterpret_cast<const uint32_t*>(Ql + (br + g)     * AT_LD + kk + tg * 2 + 8);
            al[3] = *reinterpret_cast<const uint32_t*>(Ql + (br + g + 8) * AT_LD + kk + tg * 2 + 8);
            #pragma unroll
            for (int t = 0; t < 8; t++) {
                const int n = t * 8 + g;
                uint32_t bh[2], bl[2];
                bh[0] = *reinterpret_cast<const uint32_t*>(Kh + n * AT_LD + kk + tg * 2);
                bh[1] = *reinterpret_cast<const uint32_t*>(Kh + n * AT_LD + kk + tg * 2 + 8);
                bl[0] = *reinterpret_cast<const uint32_t*>(Kl + n * AT_LD + kk + tg * 2);
                bl[1] = *reinterpret_cast<const uint32_t*>(Kl + n * AT_LD + kk + tg * 2 + 8);
                mma_bf16(s[t], ah, bh);
                mma_bf16(s[t], ah, bl);
                mma_bf16(s[t], al, bh);
            }
        }

        // ---- scale + causal + att_mask ----
        const int r0 = q0 + wp * 16 + g;
        const int r1 = r0 + 8;
        #pragma unroll
        for (int t = 0; t < 8; t++) {
            const int col0 = j * 64 + t * 8 + tg * 2;
            const int col1 = col0 + 1;
            const int mk0 = att_mask[b * Ss + col0];
            const int mk1 = att_mask[b * Ss + col1];
            s[t][0] = (col0 <= r0 && mk0 != 0) ? s[t][0] * 0.125f : -INFINITY;
            s[t][1] = (col1 <= r0 && mk1 != 0) ? s[t][1] * 0.125f : -INFINITY;
            s[t][2] = (col0 <= r1 && mk0 != 0) ? s[t][2] * 0.125f : -INFINITY;
            s[t][3] = (col1 <= r1 && mk1 != 0) ? s[t][3] * 0.125f : -INFINITY;
        }

        // ---- online softmax (row = quad of 4 lanes) ----
        float rm0 = -INFINITY, rm1 = -INFINITY;
        #pragma unroll
        for (int t = 0; t < 8; t++) {
            rm0 = fmaxf(rm0, fmaxf(s[t][0], s[t][1]));
            rm1 = fmaxf(rm1, fmaxf(s[t][2], s[t][3]));
        }
        rm0 = fmaxf(rm0, __shfl_xor_sync(0xffffffffu, rm0, 1));
        rm0 = fmaxf(rm0, __shfl_xor_sync(0xffffffffu, rm0, 2));
        rm1 = fmaxf(rm1, __shfl_xor_sync(0xffffffffu, rm1, 1));
        rm1 = fmaxf(rm1, __shfl_xor_sync(0xffffffffu, rm1, 2));

        const float mn0 = fmaxf(m0, rm0);
        const float mn1 = fmaxf(m1, rm1);
        const float a0 = __expf(m0 - mn0);   // exp(-inf)=0 on first tile
        const float a1 = __expf(m1 - mn1);

        float rs0 = 0.0f, rs1 = 0.0f;
        #pragma unroll
        for (int t = 0; t < 8; t++) {
            s[t][0] = __expf(s[t][0] - mn0);
            s[t][1] = __expf(s[t][1] - mn0);
            s[t][2] = __expf(s[t][2] - mn1);
            s[t][3] = __expf(s[t][3] - mn1);
            rs0 += s[t][0] + s[t][1];
            rs1 += s[t][2] + s[t][3];
        }
        rs0 += __shfl_xor_sync(0xffffffffu, rs0, 1);
        rs0 += __shfl_xor_sync(0xffffffffu, rs0, 2);
        rs1 += __shfl_xor_sync(0xffffffffu, rs1, 1);
        rs1 += __shfl_xor_sync(0xffffffffu, rs1, 2);

        l0 = l0 * a0 + rs0;
        l1 = l1 * a1 + rs1;
        m0 = mn0;
        m1 = mn1;
        #pragma unroll
        for (int t = 0; t < 8; t++) {
            acc_o[t][0] *= a0;
            acc_o[t][1] *= a0;
            acc_o[t][2] *= a1;
            acc_o[t][3] *= a1;
        }

        // ---- O += P V : P from registers (split hi/lo), B = V^T ----
        #pragma unroll
        for (int kb = 0; kb < 4; kb++) {
            const int t0 = 2 * kb, t1 = 2 * kb + 1;
            uint32_t pah[4], pal[4];
            {
                float ph, pl;
                float h00, h01, h02, h03, h10, h11, h12, h13;
                float l00, l01, l02, l03, l10, l11, l12, l13;
                ph = __bfloat162float(__float2bfloat16(s[t0][0])); h00 = ph; l00 = s[t0][0] - ph;
                ph = __bfloat162float(__float2bfloat16(s[t0][1])); h01 = ph; l01 = s[t0][1] - ph;
                ph = __bfloat162float(__float2bfloat16(s[t0][2])); h02 = ph; l02 = s[t0][2] - ph;
                ph = __bfloat162float(__float2bfloat16(s[t0][3])); h03 = ph; l03 = s[t0][3] - ph;
                ph = __bfloat162float(__float2bfloat16(s[t1][0])); h10 = ph; l10 = s[t1][0] - ph;
                ph = __bfloat162float(__float2bfloat16(s[t1][1])); h11 = ph; l11 = s[t1][1] - ph;
                ph = __bfloat162float(__float2bfloat16(s[t1][2])); h12 = ph; l12 = s[t1][2] - ph;
                ph = __bfloat162float(__float2bfloat16(s[t1][3])); h13 = ph; l13 = s[t1][3] - ph;
                (void)pl;
                pah[0] = pack2(h00, h01);  // row g,   k = kb*16 + tg*2, +1
                pah[1] = pack2(h02, h03);  // row g+8
                pah[2] = pack2(h10, h11);  // row g,   k+8
                pah[3] = pack2(h12, h13);  // row g+8, k+8
                pal[0] = pack2(l00, l01);
                pal[1] = pack2(l02, l03);
                pal[2] = pack2(l10, l11);
                pal[3] = pack2(l12, l13);
            }
            #pragma unroll
            for (int t = 0; t < 8; t++) {
                const int n = t * 8 + g;        // d-dim
                uint32_t bh[2], bl[2];
                bh[0] = *reinterpret_cast<const uint32_t*>(Vh + n * AT_LD + kb * 16 + tg * 2);
                bh[1] = *reinterpret_cast<const uint32_t*>(Vh + n * AT_LD + kb * 16 + tg * 2 + 8);
                bl[0] = *reinterpret_cast<const uint32_t*>(Vl + n * AT_LD + kb * 16 + tg * 2);
                bl[1] = *reinterpret_cast<const uint32_t*>(Vl + n * AT_LD + kb * 16 + tg * 2 + 8);
                mma_bf16(acc_o[t], pah, bh);
                mma_bf16(acc_o[t], pah, bl);
                mma_bf16(acc_o[t], pal, bh);
            }
        }
    }

    // ---- Epilogue: O / l -> g_y [B,S,E] ----
    const float inv0 = 1.0f / l0;
    const float inv1 = 1.0f / l1;
    const int r0g = q0 + wp * 16 + g;
    const size_t row0 = ((size_t)(b * Ss + r0g)) * Ee + h * 64;
    const size_t row1 = ((size_t)(b * Ss + r0g + 8)) * Ee + h * 64;
    #pragma unroll
    for (int t = 0; t < 8; t++) {
        const int c = t * 8 + tg * 2;
        g_y[row0 + c]     = acc_o[t][0] * inv0;
        g_y[row0 + c + 1] = acc_o[t][1] * inv0;
        g_y[row1 + c]     = acc_o[t][2] * inv1;
        g_y[row1 + c + 1] = acc_o[t][3] * inv1;
    }
}

// ---------------------------------------------------------------------------
// Kernel 3: out = y @ W_proj + b_proj (byte-identical to R11-passing)
// ---------------------------------------------------------------------------
__global__ __launch_bounds__(256) void proj_gemm_kernel(
    const float* __restrict__ W,      // [768, 768]
    const float* __restrict__ bias,   // [768]
    float* __restrict__ out)          // [M, 768]
{
    __shared__ __nv_bfloat16 Ah[GBM * A_LD];
    __shared__ __nv_bfloat16 Al[GBM * A_LD];
    __shared__ __nv_bfloat16 Bth[GBN * BT_LD];
    __shared__ __nv_bfloat16 Btl[GBN * BT_LD];

    const int tid = threadIdx.x;
    const int m0 = blockIdx.y * GBM;
    const int n0 = blockIdx.x * GBN;

    const int w    = tid >> 5;
    const int wm   = w >> 1;
    const int wn   = w & 1;
    const int lane = tid & 31;
    const int g    = lane >> 2;
    const int tg   = lane & 3;

    float acc[2][4][4] = {};

    for (int k0 = 0; k0 < Kdim; k0 += GBK) {
        #pragma unroll
        for (int p = 0; p < 4; p++) {
            const int id = p * 256 + tid;
            const int r = id >> 3;
            const int c4 = id & 7;
            const float4 v4 = *reinterpret_cast<const float4*>(
                g_y + (size_t)(m0 + r) * Kdim + k0 + c4 * 4);
            const float vv[4] = {v4.x, v4.y, v4.z, v4.w};
            float hi[4], lo[4];
            #pragma unroll
            for (int q = 0; q < 4; q++) {
                hi[q] = __bfloat162float(__float2bfloat16(vv[q]));
                lo[q] = vv[q] - hi[q];
            }
            uint32_t* ah32 = reinterpret_cast<uint32_t*>(Ah + r * A_LD + c4 * 4);
            uint32_t* al32 = reinterpret_cast<uint32_t*>(Al + r * A_LD + c4 * 4);
            ah32[0] = pack2(hi[0], hi[1]); ah32[1] = pack2(hi[2], hi[3]);
            al32[0] = pack2(lo[0], lo[1]); al32[1] = pack2(lo[2], lo[3]);
        }
        #pragma unroll
        for (int p = 0; p < 2; p++) {
            const int id = p * 256 + tid;
            const int r = id >> 4;
            const int c4 = id & 15;
            const float4 v4 = *reinterpret_cast<const float4*>(
                W + (size_t)(k0 + r) * Ee + n0 + c4 * 4);
            const float vv[4] = {v4.x, v4.y, v4.z, v4.w};
            #pragma unroll
            for (int q = 0; q < 4; q++) {
                const float h = __bfloat162float(__float2bfloat16(vv[q]));
                const float l = vv[q] - h;
                Bth[(c4 * 4 + q) * BT_LD + r] = __float2bfloat16(h);
                Btl[(c4 * 4 + q) * BT_LD + r] = __float2bfloat16(l);
            }
        }
        __syncthreads();

        #pragma unroll
        for (int ks = 0; ks < 2; ks++) {
            const int kk = ks * 16;
            uint32_t ahf[2][4], alf[2][4];
            #pragma unroll
            for (int i = 0; i < 2; i++) {
                const int br = wm * 32 + i * 16;
                ahf[i][0] = *reinterpret_cast<const uint32_t*>(Ah + (br + g)     * A_LD + kk + tg * 2);
                ahf[i][1] = *reinterpret_cast<const uint32_t*>(Ah + (br + g + 8) * A_LD + kk + tg * 2);
                ahf[i][2] = *reinterpret_cast<const uint32_t*>(Ah + (br + g)     * A_LD + kk + tg * 2 + 8);
                ahf[i][3] = *reinterpret_cast<const uint32_t*>(Ah + (br + g + 8) * A_LD + kk + tg * 2 + 8);
                alf[i][0] = *reinterpret_cast<const uint32_t*>(Al + (br + g)     * A_LD + kk + tg * 2);
                alf[i][1] = *reinterpret_cast<const uint32_t*>(Al + (br + g + 8) * A_LD + kk + tg * 2);
                alf[i][2] = *reinterpret_cast<const uint32_t*>(Al + (br + g)     * A_LD + kk + tg * 2 + 8);
                alf[i][3] = *reinterpret_cast<const uint32_t*>(Al + (br + g + 8) * A_LD + kk + tg * 2 + 8);
            }
            uint32_t bhf[4][2], blf[4][2];
            #pragma unroll
            for (int j = 0; j < 4; j++) {
                const int n = wn * 32 + j * 8 + g;
                bhf[j][0] = *reinterpret_cast<const uint32_t*>(Bth + n * BT_LD + kk + tg * 2);
                bhf[j][1] = *reinterpret_cast<const uint32_t*>(Bth + n * BT_LD + kk + tg * 2 + 8);
                blf[j][0] = *reinterpret_cast<const uint32_t*>(Btl + n * BT_LD + kk + tg * 2);
                blf[j][1] = *reinterpret_cast<const uint32_t*>(Btl + n * BT_LD + kk + tg * 2 + 8);
            }
            #pragma unroll
            for (int i = 0; i < 2; i++)
                #pragma unroll
                for (int j = 0; j < 4; j++) {
                    mma_bf16(acc[i][j], ahf[i], bhf[j]);
                    mma_bf16(acc[i][j], ahf[i], blf[j]);
                    mma_bf16(acc[i][j], alf[i], bhf[j]);
                }
        }
        __syncthreads();
    }

    #pragma unroll
    for (int i = 0; i < 2; i++) {
        #pragma unroll
        for (int j = 0; j < 4; j++) {
            const int colb = n0 + wn * 32 + j * 8 + tg * 2;
            #pragma unroll
            for (int e4 = 0; e4 < 4; e4++) {
                const int m = m0 + wm * 32 + i * 16 + g + (e4 >= 2 ? 8 : 0);
                const int n = colb + (e4 & 1);
                out[(size_t)m * Ee + n] = acc[i][j][e4] + bias[n];
            }
        }
    }
}

// ---------------------------------------------------------------------------
// Launch
// ---------------------------------------------------------------------------
extern "C" void kernel_launch(void* const* d_in, const int* in_sizes, int n_in,
                              void* d_out, int out_size)
{
    const float* x      = (const float*)d_in[0];  // [B,S,E]
    const float* W_attn = (const float*)d_in[1];  // [E,3E]
    const float* b_attn = (const float*)d_in[2];  // [3E]
    const float* W_proj = (const float*)d_in[3];  // [E,E]
    const float* b_proj = (const float*)d_in[4];  // [E]
    const int* att_mask = (const int*)d_in[5];    // [B,S]
    float* out = (float*)d_out;

    // Opt-in to >48KB dynamic smem for the attention kernel (idempotent)
    cudaFuncSetAttribute(attn_kernel,
                         cudaFuncAttributeMaxDynamicSharedMemorySize,
                         (int)ATT_SMEM_BYTES);

    {
        dim3 grid(N_QKV / GBN, Mrows / GBM);   // 36 x 64
        qkv_gemm_kernel<<<grid, 256>>>(x, W_attn, b_attn);
    }
    {
        dim3 grid(Ss / QROWS, Hh, Bb);         // 16 x 12 x 4
        attn_kernel<<<grid, 256, ATT_SMEM_BYTES>>>(att_mask);
    }
    {
        dim3 grid(Ee / GBN, Mrows / GBM);      // 12 x 64
        proj_gemm_kernel<<<grid, 256>>>(W_proj, b_proj, out);
    }
}

// round 15
// speedup vs baseline: 1.8838x; 1.2525x over previous
#include <cuda_runtime.h>
#include <cuda_bf16.h>
#include <math.h>
#include <stdint.h>

// Problem constants
constexpr int Bb = 4;
constexpr int Ss = 2048;
constexpr int Ee = 768;
constexpr int Hh = 12;
constexpr int Dd = 64;
constexpr int Mrows = Bb * Ss;      // 8192
constexpr int N_QKV = 3 * Ee;       // 2304
constexpr int Kdim = 768;

// bf16 scratch (device globals: no allocation allowed)
__device__ __nv_bfloat16 g_xh[(size_t)Mrows * Kdim];
__device__ __nv_bfloat16 g_xl[(size_t)Mrows * Kdim];
__device__ __nv_bfloat16 g_WaTh[(size_t)N_QKV * Kdim];   // [n][k]
__device__ __nv_bfloat16 g_WaTl[(size_t)N_QKV * Kdim];
__device__ __nv_bfloat16 g_WpTh[(size_t)Ee * Ee];        // [n][k]
__device__ __nv_bfloat16 g_WpTl[(size_t)Ee * Ee];
__device__ __nv_bfloat16 g_qh[(size_t)Bb * Hh * Ss * Dd];
__device__ __nv_bfloat16 g_ql[(size_t)Bb * Hh * Ss * Dd];
__device__ __nv_bfloat16 g_kh[(size_t)Bb * Hh * Ss * Dd];
__device__ __nv_bfloat16 g_kl[(size_t)Bb * Hh * Ss * Dd];
__device__ __nv_bfloat16 g_vth[(size_t)Bb * Hh * Dd * Ss];  // transposed [b,h,d,s]
__device__ __nv_bfloat16 g_vtl[(size_t)Bb * Hh * Dd * Ss];
__device__ __nv_bfloat16 g_yh[(size_t)Mrows * Ee];
__device__ __nv_bfloat16 g_yl[(size_t)Mrows * Ee];

// ---------------------------------------------------------------------------
// Shared helpers
// ---------------------------------------------------------------------------
constexpr int GBM = 128, GBN = 64, GBK = 32;
constexpr int A_LD  = GBK + 8;   // 40
constexpr int BT_LD = GBK + 8;   // 40

__device__ __forceinline__ uint32_t pack2(float v0, float v1) {
    __nv_bfloat162 t = __floats2bfloat162_rn(v0, v1);
    return *reinterpret_cast<uint32_t*>(&t);
}

__device__ __forceinline__ void split2(float v0, float v1, uint32_t& h, uint32_t& l) {
    const float h0 = __bfloat162float(__float2bfloat16(v0));
    const float h1 = __bfloat162float(__float2bfloat16(v1));
    h = pack2(h0, h1);
    l = pack2(v0 - h0, v1 - h1);
}

__device__ __forceinline__ void mma_bf16(float d[4],
                                         const uint32_t a[4],
                                         const uint32_t b[2]) {
    asm volatile(
        "mma.sync.aligned.m16n8k16.row.col.f32.bf16.bf16.f32 "
        "{%0,%1,%2,%3}, {%4,%5,%6,%7}, {%8,%9}, {%0,%1,%2,%3};\n"
        : "+f"(d[0]), "+f"(d[1]), "+f"(d[2]), "+f"(d[3])
        : "r"(a[0]), "r"(a[1]), "r"(a[2]), "r"(a[3]),
          "r"(b[0]), "r"(b[1]));
}

// ---------------------------------------------------------------------------
// Prep kernel A: split x -> g_xh/g_xl (straight layout). 8 elems/thread.
// ---------------------------------------------------------------------------
__global__ __launch_bounds__(256) void split_x_kernel(const float* __restrict__ x)
{
    const size_t base = ((size_t)blockIdx.x * 256 + threadIdx.x) * 8;
    const float4 a = *reinterpret_cast<const float4*>(x + base);
    const float4 c = *reinterpret_cast<const float4*>(x + base + 4);
    const float v[8] = {a.x, a.y, a.z, a.w, c.x, c.y, c.z, c.w};
    uint32_t hh[4], ll[4];
    #pragma unroll
    for (int q = 0; q < 4; q++) split2(v[2 * q], v[2 * q + 1], hh[q], ll[q]);
    *reinterpret_cast<uint4*>(g_xh + base) = make_uint4(hh[0], hh[1], hh[2], hh[3]);
    *reinterpret_cast<uint4*>(g_xl + base) = make_uint4(ll[0], ll[1], ll[2], ll[3]);
}

// ---------------------------------------------------------------------------
// Prep kernel B1: split + transpose W_attn [K][N_QKV] -> g_WaTh/l [N_QKV][K]
// 32x32 smem tile transpose, 256 threads (32 x 8). Writes globals directly.
// ---------------------------------------------------------------------------
__global__ __launch_bounds__(256) void split_wa_kernel(const float* __restrict__ W)
{
    __shared__ float tile[32][33];
    const int tx = threadIdx.x & 31;
    const int ty = threadIdx.x >> 5;
    const int n0 = blockIdx.x * 32;
    const int k0 = blockIdx.y * 32;

    #pragma unroll
    for (int r = ty; r < 32; r += 8)
        tile[r][tx] = W[(size_t)(k0 + r) * N_QKV + n0 + tx];
    __syncthreads();

    #pragma unroll
    for (int r = ty; r < 32; r += 8) {
        const float v = tile[tx][r];            // = W[k0+tx][n0+r]
        const float h = __bfloat162float(__float2bfloat16(v));
        g_WaTh[(size_t)(n0 + r) * Kdim + k0 + tx] = __float2bfloat16(h);
        g_WaTl[(size_t)(n0 + r) * Kdim + k0 + tx] = __float2bfloat16(v - h);
    }
}

// ---------------------------------------------------------------------------
// Prep kernel B2: split + transpose W_proj [K][E] -> g_WpTh/l [E][K]
// ---------------------------------------------------------------------------
__global__ __launch_bounds__(256) void split_wp_kernel(const float* __restrict__ W)
{
    __shared__ float tile[32][33];
    const int tx = threadIdx.x & 31;
    const int ty = threadIdx.x >> 5;
    const int n0 = blockIdx.x * 32;
    const int k0 = blockIdx.y * 32;

    #pragma unroll
    for (int r = ty; r < 32; r += 8)
        tile[r][tx] = W[(size_t)(k0 + r) * Ee + n0 + tx];
    __syncthreads();

    #pragma unroll
    for (int r = ty; r < 32; r += 8) {
        const float v = tile[tx][r];            // = W[k0+tx][n0+r]
        const float h = __bfloat162float(__float2bfloat16(v));
        g_WpTh[(size_t)(n0 + r) * Kdim + k0 + tx] = __float2bfloat16(h);
        g_WpTl[(size_t)(n0 + r) * Kdim + k0 + tx] = __float2bfloat16(v - h);
    }
}

// ---------------------------------------------------------------------------
// Kernel 1: QKV GEMM (bf16 inputs pre-split). Epilogue writes q/k packed
// bf16x2 hi/lo in [B,H,S,D] and V transposed [B,H,D,S].
// ---------------------------------------------------------------------------
__global__ __launch_bounds__(256) void qkv_gemm_kernel(const float* __restrict__ bias)
{
    __shared__ __nv_bfloat16 Ah[GBM * A_LD];
    __shared__ __nv_bfloat16 Al[GBM * A_LD];
    __shared__ __nv_bfloat16 Bth[GBN * BT_LD];
    __shared__ __nv_bfloat16 Btl[GBN * BT_LD];

    const int tid = threadIdx.x;
    const int m0 = blockIdx.y * GBM;
    const int n0 = blockIdx.x * GBN;

    const int w    = tid >> 5;
    const int wm   = w >> 1;
    const int wn   = w & 1;
    const int lane = tid & 31;
    const int g    = lane >> 2;
    const int tg   = lane & 3;

    float acc[2][4][4] = {};

    for (int k0 = 0; k0 < Kdim; k0 += GBK) {
        // A tiles: 512 uint4 per half, 2/thread per half (pure copy)
        #pragma unroll
        for (int p = 0; p < 2; p++) {
            const int id = p * 256 + tid;
            const int r = id >> 2;          // 0..127
            const int c8 = id & 3;          // 0..3 (x8 bf16)
            const size_t goff = (size_t)(m0 + r) * Kdim + k0 + c8 * 8;
            *reinterpret_cast<uint4*>(Ah + r * A_LD + c8 * 8) =
                *reinterpret_cast<const uint4*>(g_xh + goff);
            *reinterpret_cast<uint4*>(Al + r * A_LD + c8 * 8) =
                *reinterpret_cast<const uint4*>(g_xl + goff);
        }
        // B tiles: 256 uint4 per half, 1/thread per half
        {
            const int r = tid >> 2;         // 0..63
            const int c8 = tid & 3;
            const size_t goff = (size_t)(n0 + r) * Kdim + k0 + c8 * 8;
            *reinterpret_cast<uint4*>(Bth + r * BT_LD + c8 * 8) =
                *reinterpret_cast<const uint4*>(g_WaTh + goff);
            *reinterpret_cast<uint4*>(Btl + r * BT_LD + c8 * 8) =
                *reinterpret_cast<const uint4*>(g_WaTl + goff);
        }
        __syncthreads();

        #pragma unroll
        for (int ks = 0; ks < 2; ks++) {
            const int kk = ks * 16;
            uint32_t ahf[2][4], alf[2][4];
            #pragma unroll
            for (int i = 0; i < 2; i++) {
                const int br = wm * 32 + i * 16;
                ahf[i][0] = *reinterpret_cast<const uint32_t*>(Ah + (br + g)     * A_LD + kk + tg * 2);
                ahf[i][1] = *reinterpret_cast<const uint32_t*>(Ah + (br + g + 8) * A_LD + kk + tg * 2);
                ahf[i][2] = *reinterpret_cast<const uint32_t*>(Ah + (br + g)     * A_LD + kk + tg * 2 + 8);
                ahf[i][3] = *reinterpret_cast<const uint32_t*>(Ah + (br + g + 8) * A_LD + kk + tg * 2 + 8);
                alf[i][0] = *reinterpret_cast<const uint32_t*>(Al + (br + g)     * A_LD + kk + tg * 2);
                alf[i][1] = *reinterpret_cast<const uint32_t*>(Al + (br + g + 8) * A_LD + kk + tg * 2);
                alf[i][2] = *reinterpret_cast<const uint32_t*>(Al + (br + g)     * A_LD + kk + tg * 2 + 8);
                alf[i][3] = *reinterpret_cast<const uint32_t*>(Al + (br + g + 8) * A_LD + kk + tg * 2 + 8);
            }
            uint32_t bhf[4][2], blf[4][2];
            #pragma unroll
            for (int j = 0; j < 4; j++) {
                const int n = wn * 32 + j * 8 + g;
                bhf[j][0] = *reinterpret_cast<const uint32_t*>(Bth + n * BT_LD + kk + tg * 2);
                bhf[j][1] = *reinterpret_cast<const uint32_t*>(Bth + n * BT_LD + kk + tg * 2 + 8);
                blf[j][0] = *reinterpret_cast<const uint32_t*>(Btl + n * BT_LD + kk + tg * 2);
                blf[j][1] = *reinterpret_cast<const uint32_t*>(Btl + n * BT_LD + kk + tg * 2 + 8);
            }
            #pragma unroll
            for (int i = 0; i < 2; i++)
                #pragma unroll
                for (int j = 0; j < 4; j++) {
                    mma_bf16(acc[i][j], ahf[i], bhf[j]);
                    mma_bf16(acc[i][j], ahf[i], blf[j]);
                    mma_bf16(acc[i][j], alf[i], bhf[j]);
                }
        }
        __syncthreads();
    }

    // Epilogue: bias + split + scatter (q/k packed bf16x2, v transposed)
    #pragma unroll
    for (int i = 0; i < 2; i++) {
        #pragma unroll
        for (int j = 0; j < 4; j++) {
            const int colb = n0 + wn * 32 + j * 8 + tg * 2;   // even
            const float b0 = bias[colb];
            const float b1 = bias[colb + 1];
            const int which = colb / Ee;        // same for colb+1
            const int e = colb - which * Ee;
            const int hh = e >> 6;
            const int d = e & 63;               // even
            #pragma unroll
            for (int half = 0; half < 2; half++) {   // half 0: row g; 1: row g+8
                const int m = m0 + wm * 32 + i * 16 + g + half * 8;
                const int bb = m >> 11;
                const int s = m & 2047;
                const float v0 = acc[i][j][half * 2 + 0] + b0;
                const float v1 = acc[i][j][half * 2 + 1] + b1;
                if (which < 2) {
                    uint32_t hpk, lpk;
                    split2(v0, v1, hpk, lpk);
                    const size_t idx = (((size_t)(bb * Hh + hh)) * Ss + s) * Dd + d;
                    __nv_bfloat16* dh = (which == 0) ? g_qh : g_kh;
                    __nv_bfloat16* dl = (which == 0) ? g_ql : g_kl;
                    *reinterpret_cast<uint32_t*>(dh + idx) = hpk;
                    *reinterpret_cast<uint32_t*>(dl + idx) = lpk;
                } else {
                    const float h0 = __bfloat162float(__float2bfloat16(v0));
                    const float h1 = __bfloat162float(__float2bfloat16(v1));
                    const size_t idxT = (((size_t)(bb * Hh + hh)) * Dd + d) * Ss + s;
                    g_vth[idxT]      = __float2bfloat16(h0);
                    g_vtl[idxT]      = __float2bfloat16(v0 - h0);
                    g_vth[idxT + Ss] = __float2bfloat16(h1);
                    g_vtl[idxT + Ss] = __float2bfloat16(v1 - h1);
                }
            }
        }
    }
}

// ---------------------------------------------------------------------------
// Kernel 2: tensor-core flash attention (pre-split bf16 inputs).
// Structure identical to R13-passing version; loaders are pure copies.
// ---------------------------------------------------------------------------
constexpr int QROWS = 128;
constexpr int AT_LD = 72;   // 64 + 8 pad
constexpr int OFF_QH = 0;
constexpr int OFF_QL = OFF_QH + QROWS * AT_LD;
constexpr int OFF_KH = OFF_QL + QROWS * AT_LD;
constexpr int OFF_KL = OFF_KH + 64 * AT_LD;
constexpr int OFF_VH = OFF_KL + 64 * AT_LD;
constexpr int OFF_VL = OFF_VH + 64 * AT_LD;
constexpr size_t ATT_SMEM_BYTES = (size_t)(OFF_VL + 64 * AT_LD) * 2;  // 73728 B

__global__ __launch_bounds__(256) void attn_kernel(const int* __restrict__ att_mask)
{
    extern __shared__ __nv_bfloat16 smb[];
    __nv_bfloat16* Qh = smb + OFF_QH;
    __nv_bfloat16* Ql = smb + OFF_QL;
    __nv_bfloat16* Kh = smb + OFF_KH;
    __nv_bfloat16* Kl = smb + OFF_KL;
    __nv_bfloat16* Vh = smb + OFF_VH;   // [d][key]
    __nv_bfloat16* Vl = smb + OFF_VL;

    const int tid  = threadIdx.x;
    const int wp   = tid >> 5;
    const int lane = tid & 31;
    const int g    = lane >> 2;
    const int tg   = lane & 3;

    const int qb = blockIdx.x;
    const int h  = blockIdx.y;
    const int b  = blockIdx.z;
    const size_t head_base = ((size_t)(b * Hh + h)) * Ss * Dd;   // q/k layout
    const size_t vt_base   = ((size_t)(b * Hh + h)) * Dd * Ss;   // v^T layout
    const int q0 = qb * QROWS;

    // Q tile copy: 1024 uint4 per half, 4/thread per half
    #pragma unroll
    for (int p = 0; p < 4; p++) {
        const int id = p * 256 + tid;
        const int r = id >> 3;
        const int c8 = id & 7;
        const size_t goff = head_base + (size_t)(q0 + r) * Dd + c8 * 8;
        *reinterpret_cast<uint4*>(Qh + r * AT_LD + c8 * 8) =
            *reinterpret_cast<const uint4*>(g_qh + goff);
        *reinterpret_cast<uint4*>(Ql + r * AT_LD + c8 * 8) =
            *reinterpret_cast<const uint4*>(g_ql + goff);
    }

    float m0 = -INFINITY, m1 = -INFINITY, l0 = 0.0f, l1 = 0.0f;
    float acc_o[8][4] = {};

    const int jmax = 2 * qb + 1;
    for (int j = 0; j <= jmax; j++) {
        __syncthreads();
        // K tile: 512 uint4 per half, 2/thread per half
        #pragma unroll
        for (int p = 0; p < 2; p++) {
            const int id = p * 256 + tid;
            const int r = id >> 3;          // key 0..63
            const int c8 = id & 7;
            const size_t goff = head_base + (size_t)(j * 64 + r) * Dd + c8 * 8;
            *reinterpret_cast<uint4*>(Kh + r * AT_LD + c8 * 8) =
                *reinterpret_cast<const uint4*>(g_kh + goff);
            *reinterpret_cast<uint4*>(Kl + r * AT_LD + c8 * 8) =
                *reinterpret_cast<const uint4*>(g_kl + goff);
        }
        // V tile (already transposed in global): 512 uint4 per half
        #pragma unroll
        for (int p = 0; p < 2; p++) {
            const int id = p * 256 + tid;
            const int r = id >> 3;          // d 0..63
            const int c8 = id & 7;          // key group
            const size_t goff = vt_base + (size_t)r * Ss + j * 64 + c8 * 8;
            *reinterpret_cast<uint4*>(Vh + r * AT_LD + c8 * 8) =
                *reinterpret_cast<const uint4*>(g_vth + goff);
            *reinterpret_cast<uint4*>(Vl + r * AT_LD + c8 * 8) =
                *reinterpret_cast<const uint4*>(g_vtl + goff);
        }
        __syncthreads();

        // ---- S = Q K^T ----
        float s[8][4] = {};
        #pragma unroll
        for (int kb = 0; kb < 4; kb++) {
            const int kk = kb * 16;
            uint32_t ah[4], al[4];
            const int br = wp * 16;
            ah[0] = *reinterpret_cast<const uint32_t*>(Qh + (br + g)     * AT_LD + kk + tg * 2);
            ah[1] = *reinterpret_cast<const uint32_t*>(Qh + (br + g + 8) * AT_LD + kk + tg * 2);
            ah[2] = *reinterpret_cast<const uint32_t*>(Qh + (br + g)     * AT_LD + kk + tg * 2 + 8);
            ah[3] = *reinterpret_cast<const uint32_t*>(Qh + (br + g + 8) * AT_LD + kk + tg * 2 + 8);
            al[0] = *reinterpret_cast<const uint32_t*>(Ql + (br + g)     * AT_LD + kk + tg * 2);
            al[1] = *reinterpret_cast<const uint32_t*>(Ql + (br + g + 8) * AT_LD + kk + tg * 2);
            al[2] = *reinterpret_cast<const uint32_t*>(Ql + (br + g)     * AT_LD + kk + tg * 2 + 8);
            al[3] = *reinterpret_cast<const uint32_t*>(Ql + (br + g + 8) * AT_LD + kk + tg * 2 + 8);
            #pragma unroll
            for (int t = 0; t < 8; t++) {
                const int n = t * 8 + g;
                uint32_t bh[2], bl[2];
                bh[0] = *reinterpret_cast<const uint32_t*>(Kh + n * AT_LD + kk + tg * 2);
                bh[1] = *reinterpret_cast<const uint32_t*>(Kh + n * AT_LD + kk + tg * 2 + 8);
                bl[0] = *reinterpret_cast<const uint32_t*>(Kl + n * AT_LD + kk + tg * 2);
                bl[1] = *reinterpret_cast<const uint32_t*>(Kl + n * AT_LD + kk + tg * 2 + 8);
                mma_bf16(s[t], ah, bh);
                mma_bf16(s[t], ah, bl);
                mma_bf16(s[t], al, bh);
            }
        }

        // ---- scale + causal + att_mask ----
        const int r0 = q0 + wp * 16 + g;
        const int r1 = r0 + 8;
        #pragma unroll
        for (int t = 0; t < 8; t++) {
            const int col0 = j * 64 + t * 8 + tg * 2;
            const int col1 = col0 + 1;
            const int mk0 = att_mask[b * Ss + col0];
            const int mk1 = att_mask[b * Ss + col1];
            s[t][0] = (col0 <= r0 && mk0 != 0) ? s[t][0] * 0.125f : -INFINITY;
            s[t][1] = (col1 <= r0 && mk1 != 0) ? s[t][1] * 0.125f : -INFINITY;
            s[t][2] = (col0 <= r1 && mk0 != 0) ? s[t][2] * 0.125f : -INFINITY;
            s[t][3] = (col1 <= r1 && mk1 != 0) ? s[t][3] * 0.125f : -INFINITY;
        }

        // ---- online softmax (quad reduction) ----
        float rm0 = -INFINITY, rm1 = -INFINITY;
        #pragma unroll
        for (int t = 0; t < 8; t++) {
            rm0 = fmaxf(rm0, fmaxf(s[t][0], s[t][1]));
            rm1 = fmaxf(rm1, fmaxf(s[t][2], s[t][3]));
        }
        rm0 = fmaxf(rm0, __shfl_xor_sync(0xffffffffu, rm0, 1));
        rm0 = fmaxf(rm0, __shfl_xor_sync(0xffffffffu, rm0, 2));
        rm1 = fmaxf(rm1, __shfl_xor_sync(0xffffffffu, rm1, 1));
        rm1 = fmaxf(rm1, __shfl_xor_sync(0xffffffffu, rm1, 2));

        const float mn0 = fmaxf(m0, rm0);
        const float mn1 = fmaxf(m1, rm1);
        const float a0 = __expf(m0 - mn0);
        const float a1 = __expf(m1 - mn1);

        float rs0 = 0.0f, rs1 = 0.0f;
        #pragma unroll
        for (int t = 0; t < 8; t++) {
            s[t][0] = __expf(s[t][0] - mn0);
            s[t][1] = __expf(s[t][1] - mn0);
            s[t][2] = __expf(s[t][2] - mn1);
            s[t][3] = __expf(s[t][3] - mn1);
            rs0 += s[t][0] + s[t][1];
            rs1 += s[t][2] + s[t][3];
        }
        rs0 += __shfl_xor_sync(0xffffffffu, rs0, 1);
        rs0 += __shfl_xor_sync(0xffffffffu, rs0, 2);
        rs1 += __shfl_xor_sync(0xffffffffu, rs1, 1);
        rs1 += __shfl_xor_sync(0xffffffffu, rs1, 2);

        l0 = l0 * a0 + rs0;
        l1 = l1 * a1 + rs1;
        m0 = mn0;
        m1 = mn1;
        #pragma unroll
        for (int t = 0; t < 8; t++) {
            acc_o[t][0] *= a0;
            acc_o[t][1] *= a0;
            acc_o[t][2] *= a1;
            acc_o[t][3] *= a1;
        }

        // ---- O += P V (P register-resident, split hi/lo) ----
        #pragma unroll
        for (int kb = 0; kb < 4; kb++) {
            const int t0 = 2 * kb, t1 = 2 * kb + 1;
            uint32_t pah[4], pal[4];
            split2(s[t0][0], s[t0][1], pah[0], pal[0]);
            split2(s[t0][2], s[t0][3], pah[1], pal[1]);
            split2(s[t1][0], s[t1][1], pah[2], pal[2]);
            split2(s[t1][2], s[t1][3], pah[3], pal[3]);
            #pragma unroll
            for (int t = 0; t < 8; t++) {
                const int n = t * 8 + g;
                uint32_t bh[2], bl[2];
                bh[0] = *reinterpret_cast<const uint32_t*>(Vh + n * AT_LD + kb * 16 + tg * 2);
                bh[1] = *reinterpret_cast<const uint32_t*>(Vh + n * AT_LD + kb * 16 + tg * 2 + 8);
                bl[0] = *reinterpret_cast<const uint32_t*>(Vl + n * AT_LD + kb * 16 + tg * 2);
                bl[1] = *reinterpret_cast<const uint32_t*>(Vl + n * AT_LD + kb * 16 + tg * 2 + 8);
                mma_bf16(acc_o[t], pah, bh);
                mma_bf16(acc_o[t], pah, bl);
                mma_bf16(acc_o[t], pal, bh);
            }
        }
    }

    // ---- Epilogue: O / l -> g_yh/g_yl packed bf16x2 ----
    const float inv0 = 1.0f / l0;
    const float inv1 = 1.0f / l1;
    const int r0g = q0 + wp * 16 + g;
    const size_t row0 = ((size_t)(b * Ss + r0g)) * Ee + h * 64;
    const size_t row1 = ((size_t)(b * Ss + r0g + 8)) * Ee + h * 64;
    #pragma unroll
    for (int t = 0; t < 8; t++) {
        const int c = t * 8 + tg * 2;
        uint32_t hpk, lpk;
        split2(acc_o[t][0] * inv0, acc_o[t][1] * inv0, hpk, lpk);
        *reinterpret_cast<uint32_t*>(g_yh + row0 + c) = hpk;
        *reinterpret_cast<uint32_t*>(g_yl + row0 + c) = lpk;
        split2(acc_o[t][2] * inv1, acc_o[t][3] * inv1, hpk, lpk);
        *reinterpret_cast<uint32_t*>(g_yh + row1 + c) = hpk;
        *reinterpret_cast<uint32_t*>(g_yl + row1 + c) = lpk;
    }
}

// ---------------------------------------------------------------------------
// Kernel 3: out = y @ W_proj + b_proj (bf16 pre-split inputs)
// ---------------------------------------------------------------------------
__global__ __launch_bounds__(256) void proj_gemm_kernel(
    const float* __restrict__ bias,
    float* __restrict__ out)
{
    __shared__ __nv_bfloat16 Ah[GBM * A_LD];
    __shared__ __nv_bfloat16 Al[GBM * A_LD];
    __shared__ __nv_bfloat16 Bth[GBN * BT_LD];
    __shared__ __nv_bfloat16 Btl[GBN * BT_LD];

    const int tid = threadIdx.x;
    const int m0 = blockIdx.y * GBM;
    const int n0 = blockIdx.x * GBN;

    const int w    = tid >> 5;
    const int wm   = w >> 1;
    const int wn   = w & 1;
    const int lane = tid & 31;
    const int g    = lane >> 2;
    const int tg   = lane & 3;

    float acc[2][4][4] = {};

    for (int k0 = 0; k0 < Kdim; k0 += GBK) {
        #pragma unroll
        for (int p = 0; p < 2; p++) {
            const int id = p * 256 + tid;
            const int r = id >> 2;
            const int c8 = id & 3;
            const size_t goff = (size_t)(m0 + r) * Kdim + k0 + c8 * 8;
            *reinterpret_cast<uint4*>(Ah + r * A_LD + c8 * 8) =
                *reinterpret_cast<const uint4*>(g_yh + goff);
            *reinterpret_cast<uint4*>(Al + r * A_LD + c8 * 8) =
                *reinterpret_cast<const uint4*>(g_yl + goff);
        }
        {
            const int r = tid >> 2;
            const int c8 = tid & 3;
            const size_t goff = (size_t)(n0 + r) * Kdim + k0 + c8 * 8;
            *reinterpret_cast<uint4*>(Bth + r * BT_LD + c8 * 8) =
                *reinterpret_cast<const uint4*>(g_WpTh + goff);
            *reinterpret_cast<uint4*>(Btl + r * BT_LD + c8 * 8) =
                *reinterpret_cast<const uint4*>(g_WpTl + goff);
        }
        __syncthreads();

        #pragma unroll
        for (int ks = 0; ks < 2; ks++) {
            const int kk = ks * 16;
            uint32_t ahf[2][4], alf[2][4];
            #pragma unroll
            for (int i = 0; i < 2; i++) {
                const int br = wm * 32 + i * 16;
                ahf[i][0] = *reinterpret_cast<const uint32_t*>(Ah + (br + g)     * A_LD + kk + tg * 2);
                ahf[i][1] = *reinterpret_cast<const uint32_t*>(Ah + (br + g + 8) * A_LD + kk + tg * 2);
                ahf[i][2] = *reinterpret_cast<const uint32_t*>(Ah + (br + g)     * A_LD + kk + tg * 2 + 8);
                ahf[i][3] = *reinterpret_cast<const uint32_t*>(Ah + (br + g + 8) * A_LD + kk + tg * 2 + 8);
                alf[i][0] = *reinterpret_cast<const uint32_t*>(Al + (br + g)     * A_LD + kk + tg * 2);
                alf[i][1] = *reinterpret_cast<const uint32_t*>(Al + (br + g + 8) * A_LD + kk + tg * 2);
                alf[i][2] = *reinterpret_cast<const uint32_t*>(Al + (br + g)     * A_LD + kk + tg * 2 + 8);
                alf[i][3] = *reinterpret_cast<const uint32_t*>(Al + (br + g + 8) * A_LD + kk + tg * 2 + 8);
            }
            uint32_t bhf[4][2], blf[4][2];
            #pragma unroll
            for (int j = 0; j < 4; j++) {
                const int n = wn * 32 + j * 8 + g;
                bhf[j][0] = *reinterpret_cast<const uint32_t*>(Bth + n * BT_LD + kk + tg * 2);
                bhf[j][1] = *reinterpret_cast<const uint32_t*>(Bth + n * BT_LD + kk + tg * 2 + 8);
                blf[j][0] = *reinterpret_cast<const uint32_t*>(Btl + n * BT_LD + kk + tg * 2);
                blf[j][1] = *reinterpret_cast<const uint32_t*>(Btl + n * BT_LD + kk + tg * 2 + 8);
            }
            #pragma unroll
            for (int i = 0; i < 2; i++)
                #pragma unroll
                for (int j = 0; j < 4; j++) {
                    mma_bf16(acc[i][j], ahf[i], bhf[j]);
                    mma_bf16(acc[i][j], ahf[i], blf[j]);
                    mma_bf16(acc[i][j], alf[i], bhf[j]);
                }
        }
        __syncthreads();
    }

    #pragma unroll
    for (int i = 0; i < 2; i++) {
        #pragma unroll
        for (int j = 0; j < 4; j++) {
            const int colb = n0 + wn * 32 + j * 8 + tg * 2;
            #pragma unroll
            for (int e4 = 0; e4 < 4; e4++) {
                const int m = m0 + wm * 32 + i * 16 + g + (e4 >= 2 ? 8 : 0);
                const int n = colb + (e4 & 1);
                out[(size_t)m * Ee + n] = acc[i][j][e4] + bias[n];
            }
        }
    }
}

// ---------------------------------------------------------------------------
// Launch
// ---------------------------------------------------------------------------
extern "C" void kernel_launch(void* const* d_in, const int* in_sizes, int n_in,
                              void* d_out, int out_size)
{
    const float* x      = (const float*)d_in[0];  // [B,S,E]
    const float* W_attn = (const float*)d_in[1];  // [E,3E]
    const float* b_attn = (const float*)d_in[2];  // [3E]
    const float* W_proj = (const float*)d_in[3];  // [E,E]
    const float* b_proj = (const float*)d_in[4];  // [E]
    const int* att_mask = (const int*)d_in[5];    // [B,S]
    float* out = (float*)d_out;

    cudaFuncSetAttribute(attn_kernel,
                         cudaFuncAttributeMaxDynamicSharedMemorySize,
                         (int)ATT_SMEM_BYTES);

    split_x_kernel<<<(Mrows * Kdim) / 2048, 256>>>(x);
    {
        dim3 grid(N_QKV / 32, Kdim / 32);      // 72 x 24
        split_wa_kernel<<<grid, 256>>>(W_attn);
    }
    {
        dim3 grid(Ee / 32, Kdim / 32);         // 24 x 24
        split_wp_kernel<<<grid, 256>>>(W_proj);
    }
    {
        dim3 grid(N_QKV / GBN, Mrows / GBM);   // 36 x 64
        qkv_gemm_kernel<<<grid, 256>>>(b_attn);
    }
    {
        dim3 grid(Ss / QROWS, Hh, Bb);         // 16 x 12 x 4
        attn_kernel<<<grid, 256, ATT_SMEM_BYTES>>>(att_mask);
    }
    {
        dim3 grid(Ee / GBN, Mrows / GBM);      // 12 x 64
        proj_gemm_kernel<<<grid, 256>>>(b_proj, out);
    }
}